// round 1
// baseline (speedup 1.0000x reference)
#include <cuda_runtime.h>

// PScan: Y_t = A_t @ Y_{t-1} + X_t  (Y_0 = X_0), per (b,c) chain.
// Shapes: A,X,Y = [B=4, L=2048, C=16, 16, 16] fp32, row-major.
// Three-kernel chunked scan:
//   phase1: per 64-step chunk, compute aggregate (P = prod A, Z = local solution)
//   phase2: sequential scan of 32 chunk aggregates per chain -> carries
//   phase3: re-run recurrence per chunk from its carry, write Y.

#define BB 4
#define LL 2048
#define CC 16
#define TT 64                 // chunk length (timesteps)
#define NCHUNK (LL / TT)      // 32 chunks per chain
#define CHAINS (BB * CC)      // 64 chains
#define TOTCHUNK (CHAINS * NCHUNK)  // 2048
#define STEP_STRIDE (CC * 256)      // elements between t and t+1 for fixed (b,c)

typedef unsigned long long u64;

// Scratch: per-chunk aggregates and carries (each 16x16 matrix = 256 floats)
__device__ float g_Pagg[TOTCHUNK * 256];
__device__ float g_Zagg[TOTCHUNK * 256];
__device__ float g_carry[TOTCHUNK * 256];

// ---- packed fp32x2 helpers (Blackwell FFMA2 path: PTX only) ----
__device__ __forceinline__ u64 ffma2(u64 a, u64 b, u64 c) {
    u64 d;
    asm("fma.rn.f32x2 %0, %1, %2, %3;" : "=l"(d) : "l"(a), "l"(b), "l"(c));
    return d;
}
__device__ __forceinline__ u64 pack2(float lo, float hi) {
    u64 d;
    asm("mov.b64 %0, {%1, %2};" : "=l"(d) : "f"(lo), "f"(hi));
    return d;
}
__device__ __forceinline__ void unpack2(u64 v, float& lo, float& hi) {
    asm("mov.b64 {%0, %1}, %2;" : "=f"(lo), "=f"(hi) : "l"(v));
}

// ============================================================================
// Phase 1: chunk aggregates.
// One warp per chunk. Lanes 0-15: Z columns (init 0, add X each step).
// Lanes 16-31: P columns (init identity, no X).
// A_t, X_t staged to smem cooperatively (lanes 0-15 stage A, 16-31 stage X).
// ============================================================================
__global__ void __launch_bounds__(256, 2) phase1_kernel(
    const float* __restrict__ A, const float* __restrict__ X)
{
    __shared__ float sm[8][512];  // per-warp: [0:256) = A_t, [256:512) = X_t

    const int wid  = threadIdx.x >> 5;
    const int lane = threadIdx.x & 31;
    const int w    = blockIdx.x * 8 + wid;          // global chunk id 0..2047
    const int chain = w / NCHUNK;
    const int chunk = w % NCHUNK;
    const int b = chain >> 4;
    const int c = chain & 15;
    const int t0 = chunk * TT;
    const int col = lane & 15;
    const bool zside = (lane < 16);

    float* As = sm[wid];
    float* Xs = As + 256;

    const int base0 = ((b * LL + t0) * CC + c) * 256;
    const float* src = (zside ? A : X) + base0 + col * 4;

    // preload step 0 into smem
    float4 pf[4];
#pragma unroll
    for (int q = 0; q < 4; q++) pf[q] = *(const float4*)(src + q * 64);
    {
        float* dst = (zside ? As : Xs) + col * 4;
#pragma unroll
        for (int q = 0; q < 4; q++) *(float4*)(dst + q * 64) = pf[q];
    }
    __syncwarp();

    // init column registers (packed pairs over row index)
    u64 ypk[8];
#pragma unroll
    for (int m = 0; m < 8; m++) {
        float lo = 0.f, hi = 0.f;
        if (!zside) {                 // identity column for P
            if (col == 2 * m)     lo = 1.f;
            if (col == 2 * m + 1) hi = 1.f;
        }
        ypk[m] = pack2(lo, hi);
    }

    for (int t = 0; t < TT; t++) {
        // prefetch step t+1 into registers (hidden behind compute)
        if (t + 1 < TT) {
            const float* s2 = src + (t + 1) * STEP_STRIDE;
#pragma unroll
            for (int q = 0; q < 4; q++) pf[q] = *(const float4*)(s2 + q * 64);
        }

        // y_new[i] = sum_k A[i,k] * y[k] (+ X[i,col] for Z lanes)
        float yn[16];
#pragma unroll
        for (int i = 0; i < 16; i++) {
            const u64* arow = (const u64*)(As + i * 16);  // (A[i,2m], A[i,2m+1])
            u64 acc = 0ull;
#pragma unroll
            for (int m = 0; m < 8; m++) acc = ffma2(arow[m], ypk[m], acc);
            float alo, ahi;
            unpack2(acc, alo, ahi);
            float xv = zside ? Xs[i * 16 + col] : 0.f;
            yn[i] = alo + ahi + xv;
        }
#pragma unroll
        for (int m = 0; m < 8; m++) ypk[m] = pack2(yn[2 * m], yn[2 * m + 1]);

        __syncwarp();
        if (t + 1 < TT) {
            float* dst = (zside ? As : Xs) + col * 4;
#pragma unroll
            for (int q = 0; q < 4; q++) *(float4*)(dst + q * 64) = pf[q];
        }
        __syncwarp();
    }

    // store aggregates: Z columns -> g_Zagg, P columns -> g_Pagg
    float* agg = zside ? g_Zagg : g_Pagg;
    const int aggBase = w * 256;
    float cl[16];
#pragma unroll
    for (int m = 0; m < 8; m++) unpack2(ypk[m], cl[2 * m], cl[2 * m + 1]);
#pragma unroll
    for (int i = 0; i < 16; i++) agg[aggBase + i * 16 + col] = cl[i];
}

// ============================================================================
// Phase 2: scan chunk aggregates per chain (sequential over 32 chunks).
// One block (32 threads) per chain; lanes 0-15 each own a carry column.
// carry_{c+1} = Pagg_c @ carry_c + Zagg_c ;  g_carry[c] = state BEFORE chunk c.
// ============================================================================
__global__ void phase2_kernel()
{
    const int chain = blockIdx.x;
    const int lane  = threadIdx.x;
    if (lane >= 16) return;
    const int col = lane;

    u64 ypk[8];
#pragma unroll
    for (int m = 0; m < 8; m++) ypk[m] = 0ull;

    for (int cix = 0; cix < NCHUNK; cix++) {
        const int base = (chain * NCHUNK + cix) * 256;

        // publish carry (state before chunk cix)
        float cl[16];
#pragma unroll
        for (int m = 0; m < 8; m++) unpack2(ypk[m], cl[2 * m], cl[2 * m + 1]);
#pragma unroll
        for (int i = 0; i < 16; i++) g_carry[base + i * 16 + col] = cl[i];

        // carry = Pagg @ carry + Zagg_col
        float yn[16];
#pragma unroll
        for (int i = 0; i < 16; i++) {
            const u64* prow = (const u64*)(g_Pagg + base + i * 16);
            u64 acc = 0ull;
#pragma unroll
            for (int m = 0; m < 8; m++) acc = ffma2(prow[m], ypk[m], acc);
            float alo, ahi;
            unpack2(acc, alo, ahi);
            yn[i] = alo + ahi + g_Zagg[base + i * 16 + col];
        }
#pragma unroll
        for (int m = 0; m < 8; m++) ypk[m] = pack2(yn[2 * m], yn[2 * m + 1]);
    }
}

// ============================================================================
// Phase 3: final pass. One warp per chunk; lanes 0-15 run the recurrence
// from the chunk carry and write Y each step; lanes 16-31 help stage X.
// ============================================================================
__global__ void __launch_bounds__(256, 2) phase3_kernel(
    const float* __restrict__ A, const float* __restrict__ X,
    float* __restrict__ Y)
{
    __shared__ float sm[8][512];

    const int wid  = threadIdx.x >> 5;
    const int lane = threadIdx.x & 31;
    const int w    = blockIdx.x * 8 + wid;
    const int chain = w / NCHUNK;
    const int chunk = w % NCHUNK;
    const int b = chain >> 4;
    const int c = chain & 15;
    const int t0 = chunk * TT;
    const int col = lane & 15;
    const bool zside = (lane < 16);

    float* As = sm[wid];
    float* Xs = As + 256;

    const int base0 = ((b * LL + t0) * CC + c) * 256;
    const float* src = (zside ? A : X) + base0 + col * 4;

    float4 pf[4];
#pragma unroll
    for (int q = 0; q < 4; q++) pf[q] = *(const float4*)(src + q * 64);
    {
        float* dst = (zside ? As : Xs) + col * 4;
#pragma unroll
        for (int q = 0; q < 4; q++) *(float4*)(dst + q * 64) = pf[q];
    }
    __syncwarp();

    // init from carry (state before this chunk)
    u64 ypk[8];
    {
        const int cb = w * 256;
        float cl[16];
#pragma unroll
        for (int i = 0; i < 16; i++)
            cl[i] = zside ? g_carry[cb + i * 16 + col] : 0.f;
#pragma unroll
        for (int m = 0; m < 8; m++) ypk[m] = pack2(cl[2 * m], cl[2 * m + 1]);
    }

    for (int t = 0; t < TT; t++) {
        if (t + 1 < TT) {
            const float* s2 = src + (t + 1) * STEP_STRIDE;
#pragma unroll
            for (int q = 0; q < 4; q++) pf[q] = *(const float4*)(s2 + q * 64);
        }

        if (zside) {
            float yn[16];
#pragma unroll
            for (int i = 0; i < 16; i++) {
                const u64* arow = (const u64*)(As + i * 16);
                u64 acc = 0ull;
#pragma unroll
                for (int m = 0; m < 8; m++) acc = ffma2(arow[m], ypk[m], acc);
                float alo, ahi;
                unpack2(acc, alo, ahi);
                yn[i] = alo + ahi + Xs[i * 16 + col];
            }
            // write Y_t
            float* out = Y + base0 + t * STEP_STRIDE + col;
#pragma unroll
            for (int i = 0; i < 16; i++) out[i * 16] = yn[i];
#pragma unroll
            for (int m = 0; m < 8; m++) ypk[m] = pack2(yn[2 * m], yn[2 * m + 1]);
        }

        __syncwarp();
        if (t + 1 < TT) {
            float* dst = (zside ? As : Xs) + col * 4;
#pragma unroll
            for (int q = 0; q < 4; q++) *(float4*)(dst + q * 64) = pf[q];
        }
        __syncwarp();
    }
}

// ============================================================================
extern "C" void kernel_launch(void* const* d_in, const int* in_sizes, int n_in,
                              void* d_out, int out_size)
{
    const float* A = (const float*)d_in[0];
    const float* X = (const float*)d_in[1];
    float* Y = (float*)d_out;

    phase1_kernel<<<TOTCHUNK / 8, 256>>>(A, X);
    phase2_kernel<<<CHAINS, 32>>>();
    phase3_kernel<<<TOTCHUNK / 8, 256>>>(A, X, Y);
}

// round 2
// speedup vs baseline: 1.5919x; 1.5919x over previous
#include <cuda_runtime.h>

// PScan: Y_t = A_t @ Y_{t-1} + X_t  (Y_0 = X_0), per (b,c) chain.
// Shapes: A,X,Y = [B=4, L=2048, C=16, 16, 16] fp32, row-major.
// Three-kernel chunked scan, LDS.128-optimized.

#define BB 4
#define LL 2048
#define CC 16
#define TT 64
#define NCHUNK (LL / TT)            // 32
#define CHAINS (BB * CC)            // 64
#define TOTCHUNK (CHAINS * NCHUNK)  // 2048
#define STEP_STRIDE (CC * 256)

typedef unsigned long long u64;

__device__ float g_Pagg[TOTCHUNK * 256];
__device__ float g_Zagg[TOTCHUNK * 256];
__device__ float g_carry[TOTCHUNK * 256];

__device__ __forceinline__ u64 ffma2(u64 a, u64 b, u64 c) {
    u64 d;
    asm("fma.rn.f32x2 %0, %1, %2, %3;" : "=l"(d) : "l"(a), "l"(b), "l"(c));
    return d;
}
__device__ __forceinline__ u64 pack2(float lo, float hi) {
    u64 d;
    asm("mov.b64 %0, {%1, %2};" : "=l"(d) : "f"(lo), "f"(hi));
    return d;
}
__device__ __forceinline__ void unpack2(u64 v, float& lo, float& hi) {
    asm("mov.b64 {%0, %1}, %2;" : "=f"(lo), "=f"(hi) : "l"(v));
}

// ============================================================================
// Phase 1: chunk aggregates. One warp per chunk; 64-thread blocks (2 warps).
// Lanes 0-15: Z columns (init 0, + X). Lanes 16-31: P columns (init I).
// A_t/X_t double-buffered in smem; rows read as LDS.128 broadcasts.
// ============================================================================
__global__ void __launch_bounds__(64) phase1_kernel(
    const float* __restrict__ A, const float* __restrict__ X)
{
    __shared__ __align__(16) float sm[2][2][512];  // [warp][buf][A:256|X:256]

    const int wid  = threadIdx.x >> 5;
    const int lane = threadIdx.x & 31;
    const int w    = blockIdx.x * 2 + wid;
    const int chain = w / NCHUNK;
    const int chunk = w % NCHUNK;
    const int b = chain >> 4;
    const int c = chain & 15;
    const int t0 = chunk * TT;
    const int col = lane & 15;
    const bool zside = (lane < 16);

    const int base0 = ((b * LL + t0) * CC + c) * 256;
    const float* src = (zside ? A : X) + base0 + col * 4;

    // stage step 0 into buf 0
    {
        float4 p0[4];
#pragma unroll
        for (int q = 0; q < 4; q++) p0[q] = *(const float4*)(src + q * 64);
        float* dst = sm[wid][0] + (zside ? 0 : 256) + col * 4;
#pragma unroll
        for (int q = 0; q < 4; q++) *(float4*)(dst + q * 64) = p0[q];
    }
    __syncwarp();

    u64 ypk[8];
#pragma unroll
    for (int m = 0; m < 8; m++) {
        float lo = 0.f, hi = 0.f;
        if (!zside) {
            if (col == 2 * m)     lo = 1.f;
            if (col == 2 * m + 1) hi = 1.f;
        }
        ypk[m] = pack2(lo, hi);
    }

#pragma unroll 1
    for (int t = 0; t < TT; t++) {
        float4 pf[4];
        if (t + 1 < TT) {
            const float* s2 = src + (t + 1) * STEP_STRIDE;
#pragma unroll
            for (int q = 0; q < 4; q++) pf[q] = *(const float4*)(s2 + q * 64);
        }

        const float* As = sm[wid][t & 1];
        const float* Xs = As + 256;

        float yn[16];
#pragma unroll
        for (int i = 0; i < 16; i++) {
            const ulonglong2* ar = (const ulonglong2*)(As + i * 16);
            u64 acc = 0ull;
#pragma unroll
            for (int m = 0; m < 4; m++) {
                ulonglong2 a2 = ar[m];                 // LDS.128 broadcast
                acc = ffma2(a2.x, ypk[2 * m], acc);
                acc = ffma2(a2.y, ypk[2 * m + 1], acc);
            }
            float alo, ahi;
            unpack2(acc, alo, ahi);
            float xv = zside ? Xs[i * 16 + col] : 0.f;
            yn[i] = alo + ahi + xv;
        }
#pragma unroll
        for (int m = 0; m < 8; m++) ypk[m] = pack2(yn[2 * m], yn[2 * m + 1]);

        if (t + 1 < TT) {
            float* dst = sm[wid][(t + 1) & 1] + (zside ? 0 : 256) + col * 4;
#pragma unroll
            for (int q = 0; q < 4; q++) *(float4*)(dst + q * 64) = pf[q];
        }
        __syncwarp();
    }

    float* agg = zside ? g_Zagg : g_Pagg;
    const int aggBase = w * 256;
    float cl[16];
#pragma unroll
    for (int m = 0; m < 8; m++) unpack2(ypk[m], cl[2 * m], cl[2 * m + 1]);
#pragma unroll
    for (int i = 0; i < 16; i++) agg[aggBase + i * 16 + col] = cl[i];
}

// ============================================================================
// Phase 2: per-chain scan of 32 chunk aggregates with smem prefetch pipeline.
// One 32-thread block per chain; lanes 0-15 own carry columns.
// ============================================================================
__global__ void phase2_kernel()
{
    __shared__ __align__(16) float sP[2][256];
    __shared__ __align__(16) float sZ[2][256];

    const int chain = blockIdx.x;
    const int lane  = threadIdx.x;
    const int col   = lane & 15;
    const bool zside = (lane < 16);

    // stage chunk 0
    {
        const int base = (chain * NCHUNK) * 256;
#pragma unroll
        for (int q = 0; q < 2; q++) {
            *(float4*)(sP[0] + lane * 8 + q * 4) = *(const float4*)(g_Pagg + base + lane * 8 + q * 4);
            *(float4*)(sZ[0] + lane * 8 + q * 4) = *(const float4*)(g_Zagg + base + lane * 8 + q * 4);
        }
    }
    __syncwarp();

    u64 ypk[8];
#pragma unroll
    for (int m = 0; m < 8; m++) ypk[m] = 0ull;

#pragma unroll 1
    for (int cix = 0; cix < NCHUNK; cix++) {
        const int buf = cix & 1;

        // prefetch chunk cix+1 (overlaps compute)
        if (cix + 1 < NCHUNK) {
            const int nb = (chain * NCHUNK + cix + 1) * 256;
#pragma unroll
            for (int q = 0; q < 2; q++) {
                *(float4*)(sP[buf ^ 1] + lane * 8 + q * 4) = *(const float4*)(g_Pagg + nb + lane * 8 + q * 4);
                *(float4*)(sZ[buf ^ 1] + lane * 8 + q * 4) = *(const float4*)(g_Zagg + nb + lane * 8 + q * 4);
            }
        }

        if (zside) {
            const int base = (chain * NCHUNK + cix) * 256;
            // publish carry (state BEFORE chunk cix)
            float cl[16];
#pragma unroll
            for (int m = 0; m < 8; m++) unpack2(ypk[m], cl[2 * m], cl[2 * m + 1]);
#pragma unroll
            for (int i = 0; i < 16; i++) g_carry[base + i * 16 + col] = cl[i];

            float yn[16];
#pragma unroll
            for (int i = 0; i < 16; i++) {
                const ulonglong2* pr = (const ulonglong2*)(sP[buf] + i * 16);
                u64 acc = 0ull;
#pragma unroll
                for (int m = 0; m < 4; m++) {
                    ulonglong2 a2 = pr[m];
                    acc = ffma2(a2.x, ypk[2 * m], acc);
                    acc = ffma2(a2.y, ypk[2 * m + 1], acc);
                }
                float alo, ahi;
                unpack2(acc, alo, ahi);
                yn[i] = alo + ahi + sZ[buf][i * 16 + col];
            }
#pragma unroll
            for (int m = 0; m < 8; m++) ypk[m] = pack2(yn[2 * m], yn[2 * m + 1]);
        }
        __syncwarp();
    }
}

// ============================================================================
// Phase 3: final pass. One warp per chunk; lanes 0-15 run the recurrence from
// the carry; output transposed through padded smem -> coalesced STG.128.
// ============================================================================
#define YP 18   // padded column stride (floats) in Y staging buffer

__global__ void __launch_bounds__(64) phase3_kernel(
    const float* __restrict__ A, const float* __restrict__ X,
    float* __restrict__ Y)
{
    __shared__ __align__(16) float sm[2][2][512];
    __shared__ __align__(16) float sy[2][2][16 * YP];  // [warp][buf][col*YP + i]

    const int wid  = threadIdx.x >> 5;
    const int lane = threadIdx.x & 31;
    const int w    = blockIdx.x * 2 + wid;
    const int chain = w / NCHUNK;
    const int chunk = w % NCHUNK;
    const int b = chain >> 4;
    const int c = chain & 15;
    const int t0 = chunk * TT;
    const int col = lane & 15;
    const bool zside = (lane < 16);

    const int base0 = ((b * LL + t0) * CC + c) * 256;
    const float* src = (zside ? A : X) + base0 + col * 4;

    {
        float4 p0[4];
#pragma unroll
        for (int q = 0; q < 4; q++) p0[q] = *(const float4*)(src + q * 64);
        float* dst = sm[wid][0] + (zside ? 0 : 256) + col * 4;
#pragma unroll
        for (int q = 0; q < 4; q++) *(float4*)(dst + q * 64) = p0[q];
    }

    // init state from carry (state before this chunk)
    u64 ypk[8];
    {
        const int cb = w * 256;
        float cl[16];
#pragma unroll
        for (int i = 0; i < 16; i++)
            cl[i] = zside ? g_carry[cb + i * 16 + col] : 0.f;
#pragma unroll
        for (int m = 0; m < 8; m++) ypk[m] = pack2(cl[2 * m], cl[2 * m + 1]);
    }
    __syncwarp();

    // indices for the coalesced Y write-back (all 32 lanes, 2 float4 each)
    const int e0a = lane * 4;          // element 0..127
    const int e0b = 128 + lane * 4;    // element 128..255

#pragma unroll 1
    for (int t = 0; t < TT; t++) {
        float4 pf[4];
        if (t + 1 < TT) {
            const float* s2 = src + (t + 1) * STEP_STRIDE;
#pragma unroll
            for (int q = 0; q < 4; q++) pf[q] = *(const float4*)(s2 + q * 64);
        }

        const float* As = sm[wid][t & 1];
        const float* Xs = As + 256;
        float* Ys = sy[wid][t & 1];

        if (zside) {
            float yn[16];
#pragma unroll
            for (int i = 0; i < 16; i++) {
                const ulonglong2* ar = (const ulonglong2*)(As + i * 16);
                u64 acc = 0ull;
#pragma unroll
                for (int m = 0; m < 4; m++) {
                    ulonglong2 a2 = ar[m];
                    acc = ffma2(a2.x, ypk[2 * m], acc);
                    acc = ffma2(a2.y, ypk[2 * m + 1], acc);
                }
                float alo, ahi;
                unpack2(acc, alo, ahi);
                yn[i] = alo + ahi + Xs[i * 16 + col];
            }
#pragma unroll
            for (int m = 0; m < 8; m++) ypk[m] = pack2(yn[2 * m], yn[2 * m + 1]);

            // stage column into padded smem (conflict-free STS.64)
            u64* yc = (u64*)(Ys + col * YP);
#pragma unroll
            for (int m = 0; m < 8; m++) yc[m] = ypk[m];
        }

        if (t + 1 < TT) {
            float* dst = sm[wid][(t + 1) & 1] + (zside ? 0 : 256) + col * 4;
#pragma unroll
            for (int q = 0; q < 4; q++) *(float4*)(dst + q * 64) = pf[q];
        }
        __syncwarp();

        // coalesced write of Y_t (1KB contiguous) by all 32 lanes
        {
            float* out = Y + base0 + t * STEP_STRIDE;
            float4 v;
            int i = e0a >> 4, c0 = e0a & 15;
            v.x = Ys[(c0 + 0) * YP + i];
            v.y = Ys[(c0 + 1) * YP + i];
            v.z = Ys[(c0 + 2) * YP + i];
            v.w = Ys[(c0 + 3) * YP + i];
            *(float4*)(out + e0a) = v;
            i = e0b >> 4; c0 = e0b & 15;
            v.x = Ys[(c0 + 0) * YP + i];
            v.y = Ys[(c0 + 1) * YP + i];
            v.z = Ys[(c0 + 2) * YP + i];
            v.w = Ys[(c0 + 3) * YP + i];
            *(float4*)(out + e0b) = v;
        }
    }
}

// ============================================================================
extern "C" void kernel_launch(void* const* d_in, const int* in_sizes, int n_in,
                              void* d_out, int out_size)
{
    const float* A = (const float*)d_in[0];
    const float* X = (const float*)d_in[1];
    float* Y = (float*)d_out;

    phase1_kernel<<<TOTCHUNK / 2, 64>>>(A, X);
    phase2_kernel<<<CHAINS, 32>>>();
    phase3_kernel<<<TOTCHUNK / 2, 64>>>(A, X, Y);
}